// round 9
// baseline (speedup 1.0000x reference)
#include <cuda_runtime.h>
#include <cstdint>

#define BATCH   64
#define SEQ     2048
#define DM      128
#define NT      256
#define XSTRIDE 2052
#define NWIN    64
#define WLEN    64
#define PRED    4
#define NWORK   84
#define NCTA    (BATCH + NWORK)   // 148 CTAs, all resident
#define NWTOT   (BATCH * NWIN)    // 4096 windows total; 1024 per pred... (per pred = BATCH*NWIN/4? no)
#define NWPP    (BATCH * NWIN)    // windows per pred step = 4096? NO: 64*64 = 4096 per pred
// NOTE: windows per pred = BATCH(64) * NWIN(64) = 4096?  Reference: starts shape (B, M) = (64,64)
// -> 4096 windows per pred step. Workers stride over 4096.

// ---------------- persistent device scratch (no allocs allowed) ----------------
__device__ float g_x[BATCH * XSTRIDE];            // sequence extended with predictions
__device__ float g_H4[PRED * BATCH * DM];         // global GRU state per pred step
__device__ float g_S4[PRED * BATCH * NWIN * DM];  // window GRU final states per pred step
__device__ int   g_hcnt;                          // H publishes (64 per phase)
__device__ int   g_scnt[PRED];                    // windows done per pred (-> 4096)
__device__ int   g_ycnt;                          // y publishes (64 per pred step)

typedef unsigned long long u64;

union F2U { float2 f; u64 u; };

__device__ __forceinline__ u64 fma2(u64 a, u64 b, u64 c) {
    u64 d;
    asm("fma.rn.f32x2 %0, %1, %2, %3;" : "=l"(d) : "l"(a), "l"(b), "l"(c));
    return d;
}

__device__ __forceinline__ float sigmoidf_(float x) {
    return 1.f / (1.f + __expf(-x));
}

// ---------------- threefry2x32 (exact JAX schedule) ----------------
__device__ __forceinline__ uint2 tf2x32(unsigned k0, unsigned k1, unsigned x0, unsigned x1) {
    unsigned ks2 = k0 ^ k1 ^ 0x1BD11BDAu;
    x0 += k0; x1 += k1;
#define TFR(d) { x0 += x1; x1 = __funnelshift_l(x1, x1, d); x1 ^= x0; }
    TFR(13) TFR(15) TFR(26) TFR(6)
    x0 += k1; x1 += ks2 + 1u;
    TFR(17) TFR(29) TFR(16) TFR(24)
    x0 += ks2; x1 += k0 + 2u;
    TFR(13) TFR(15) TFR(26) TFR(6)
    x0 += k0; x1 += k1 + 3u;
    TFR(17) TFR(29) TFR(16) TFR(24)
    x0 += k1; x1 += ks2 + 4u;
    TFR(13) TFR(15) TFR(26) TFR(6)
    x0 += ks2; x1 += k0 + 5u;
#undef TFR
    return make_uint2(x0, x1);
}

// starts[j] for pred `step`, window j in [0,4096), span = T - WLEN
__device__ __forceinline__ int rand_start(int step, int j, unsigned span) {
    uint2 key = tf2x32(0u, 42u, 0u, (unsigned)step);
    uint2 s0  = tf2x32(key.x, key.y, 0u, 2u);
    uint2 s1  = tf2x32(key.x, key.y, 1u, 3u);
    unsigned hi, lo;
    if (j < 2048) {
        hi = tf2x32(s0.x, s1.x, (unsigned)j, (unsigned)j + 2048u).x;
        lo = tf2x32(s0.y, s1.y, (unsigned)j, (unsigned)j + 2048u).x;
    } else {
        hi = tf2x32(s0.x, s1.x, (unsigned)j - 2048u, (unsigned)j).y;
        lo = tf2x32(s0.y, s1.y, (unsigned)j - 2048u, (unsigned)j).y;
    }
    unsigned m = 65536u % span;
    m = (m * m) % span;
    return (int)(((hi % span) * m + (lo % span)) % span);
}

// acquire-spin: thread 0 polls counter (L2, volatile), whole CTA proceeds after
__device__ __forceinline__ void wait_ctr(int* ctr, int v) {
    __syncthreads();
    if (threadIdx.x == 0) {
        while (*(volatile int*)ctr < v) { __nanosleep(64); }
    }
    __syncthreads();
}

// ---------------- kernels ----------------

__global__ void copy_x_kernel(const float* __restrict__ x) {
    int i = blockIdx.x * blockDim.x + threadIdx.x;
    if (i == 0) {
        g_hcnt = 0; g_ycnt = 0;
        for (int p = 0; p < PRED; p++) g_scnt[p] = 0;
    }
    if (i < BATCH * SEQ) {
        int b = i / SEQ, t = i % SEQ;
        g_x[b * XSTRIDE + t] = x[i];
    }
}

// ---- one GRU step, uniform across 256 threads; ONE barrier; h double-buffered ----
// Thread (j, c): j = row, c = k-half. Computes r,z,n half-dots, combines via shfl_xor(16).
// Returns new h_j (all lanes); caller's c==0 lane stores to hbuf[nxt][j].
#define GRU_STEP(XT, HSRC, HJ_OLD, HJ_NEW)                                          \
{                                                                                   \
    const float4* hp_ = (const float4*)((HSRC) + c * 64);                           \
    u64 ar0 = 0ull, ar1 = 0ull, az0 = 0ull, az1 = 0ull, an0 = 0ull, an1 = 0ull;     \
    _Pragma("unroll")                                                               \
    for (int k4 = 0; k4 < 16; k4++) {                                               \
        float4 hv = hp_[k4];                                                        \
        F2U ua_, ub_;                                                               \
        ua_.f = make_float2(hv.x, hv.y);                                            \
        ub_.f = make_float2(hv.z, hv.w);                                            \
        ar0 = fma2(wr_[2 * k4],     ua_.u, ar0);                                    \
        ar1 = fma2(wr_[2 * k4 + 1], ub_.u, ar1);                                    \
        az0 = fma2(wz_[2 * k4],     ua_.u, az0);                                    \
        az1 = fma2(wz_[2 * k4 + 1], ub_.u, az1);                                    \
        an0 = fma2(wn_[2 * k4],     ua_.u, an0);                                    \
        an1 = fma2(wn_[2 * k4 + 1], ub_.u, an1);                                    \
    }                                                                               \
    F2U r0_, r1_, z0_, z1_, n0_, n1_;                                               \
    r0_.u = ar0; r1_.u = ar1; z0_.u = az0; z1_.u = az1; n0_.u = an0; n1_.u = an1;   \
    float ghr = r0_.f.x + r0_.f.y + r1_.f.x + r1_.f.y;                              \
    float ghz = z0_.f.x + z0_.f.y + z1_.f.x + z1_.f.y;                              \
    float ghn = n0_.f.x + n0_.f.y + n1_.f.x + n1_.f.y;                              \
    ghr += __shfl_xor_sync(0xffffffffu, ghr, 16);                                   \
    ghz += __shfl_xor_sync(0xffffffffu, ghz, 16);                                   \
    ghn += __shfl_xor_sync(0xffffffffu, ghn, 16);                                   \
    float gir = (XT) * wi_r + bi_r;                                                 \
    float giz = (XT) * wi_z + bi_z;                                                 \
    float gin = (XT) * wi_n + bi_n;                                                 \
    float rr  = sigmoidf_(gir + (ghr + bh_r));                                      \
    float zz  = sigmoidf_(giz + (ghz + bh_z));                                      \
    float nn  = tanhf(gin + rr * (ghn + bh_n));                                     \
    (HJ_NEW) = (1.f - zz) * nn + zz * (HJ_OLD);                                     \
}

#define LOAD_GATE_WEIGHTS(WH)                                                       \
    u64 wr_[32], wz_[32], wn_[32];                                                  \
    {                                                                               \
        const float2* pr_ = (const float2*)((WH) + j * DM + c * 64);                \
        const float2* pz_ = (const float2*)((WH) + (128 + j) * DM + c * 64);        \
        const float2* pn_ = (const float2*)((WH) + (256 + j) * DM + c * 64);        \
        _Pragma("unroll")                                                           \
        for (int k = 0; k < 32; k++) { F2U u_; u_.f = __ldg(pr_ + k); wr_[k] = u_.u; } \
        _Pragma("unroll")                                                           \
        for (int k = 0; k < 32; k++) { F2U u_; u_.f = __ldg(pz_ + k); wz_[k] = u_.u; } \
        _Pragma("unroll")                                                           \
        for (int k = 0; k < 32; k++) { F2U u_; u_.f = __ldg(pn_ + k); wn_[k] = u_.u; } \
    }

#define LOAD_GATE_SCALARS(WI, BI, BH)                                               \
    float wi_r = __ldg((WI) + j),       bi_r = __ldg((BI) + j),       bh_r = __ldg((BH) + j);        \
    float wi_z = __ldg((WI) + 128 + j), bi_z = __ldg((BI) + 128 + j), bh_z = __ldg((BH) + 128 + j);  \
    float wi_n = __ldg((WI) + 256 + j), bi_n = __ldg((BI) + 256 + j), bh_n = __ldg((BH) + 256 + j);

// ============ global-GRU path (CTAs 0..63) ============
__device__ void global_path(int b,
    const float* __restrict__ Wi, const float* __restrict__ bi,
    const float* __restrict__ Wh, const float* __restrict__ bh)
{
    int t = threadIdx.x;
    int wid = t >> 5, lane = t & 31;
    int j = (wid << 4) + (lane & 15);
    int c = lane >> 4;

    __shared__ __align__(16) float hbuf[2][DM];

    LOAD_GATE_WEIGHTS(Wh)
    LOAD_GATE_SCALARS(Wi, bi, bh)

    if (t < DM) { hbuf[0][t] = 0.f; hbuf[1][t] = 0.f; }
    float hj = 0.f;
    __syncthreads();

    const float* xb = g_x + b * XSTRIDE;
    const int Lp[PRED] = {2048, 2048, 2049, 2050};

    int cur = 0;
    for (int p = 0; p < PRED; p++) {
        if (p >= 2) wait_ctr(&g_ycnt, BATCH * (p - 1));  // y_0..y_{p-2} present
        int L = Lp[p];
        for (int step = 0; step < L; step++) {
            float xt = (step < SEQ) ? __ldg(xb + step) : __ldcg(xb + step);
            float hn;
            GRU_STEP(xt, hbuf[cur], hj, hn)
            hj = hn;
            if (c == 0) hbuf[cur ^ 1][j] = hn;
            __syncthreads();
            cur ^= 1;
        }
        if (c == 0) g_H4[p * BATCH * DM + b * DM + j] = hj;
        __threadfence();
        __syncthreads();
        if (t == 0) atomicAdd(&g_hcnt, 1);
    }
}

// ============ worker path (CTAs 64..147): windows + stats + finalize ============
__device__ void worker_path(int w,
    const float* __restrict__ Wi, const float* __restrict__ bi,
    const float* __restrict__ Wh, const float* __restrict__ bh,
    const float* __restrict__ Wd, const float* __restrict__ bd,
    const float* __restrict__ Wc, const float* __restrict__ bc,
    float* __restrict__ out, int out_size)
{
    int t = threadIdx.x;
    int wid = t >> 5, lane = t & 31;
    int j = (wid << 4) + (lane & 15);
    int c = lane >> 4;

    __shared__ __align__(16) float hbuf[2][DM];
    __shared__ float x_s[WLEN];
    __shared__ float rs[NT], rss[NT];
    __shared__ float thresh_sh;
    __shared__ float H_sh[DM], e_s[NWIN], red[DM], qred[NWIN], se_sh;
    __shared__ int   starts_sh[NWIN];

    LOAD_GATE_WEIGHTS(Wh)
    LOAD_GATE_SCALARS(Wi, bi, bh)

    for (int p = 0; p < PRED; p++) {
        unsigned span = (unsigned)(SEQ + p - WLEN);  // 1984+p

        // ---- windows of this pred (need y_{p-2}); 4096 windows strided over workers ----
        if (p >= 2) wait_ctr(&g_ycnt, BATCH * (p - 1));
        int nwin = 0;
        for (int widx = w; widx < BATCH * NWIN; widx += NWORK) {
            int b  = widx >> 6;                      // window widx = b*NWIN + m
            int st = rand_start(p, widx, span);
            if (t < WLEN) x_s[t] = __ldcg(&g_x[b * XSTRIDE + st + t]);
            if (t < DM)   hbuf[0][t] = 0.f;
            float hj = 0.f;
            int cur = 0;
            __syncthreads();

            for (int step = 0; step < WLEN; step++) {
                float xt = x_s[step];
                float hn;
                GRU_STEP(xt, hbuf[cur], hj, hn)
                hj = hn;
                if (c == 0) hbuf[cur ^ 1][j] = hn;
                __syncthreads();
                cur ^= 1;
            }
            if (c == 0) g_S4[(p * BATCH * NWIN + widx) * DM + j] = hj;
            __syncthreads();
            nwin++;
        }
        __threadfence();
        __syncthreads();
        if (t == 0 && nwin) atomicAdd(&g_scnt[p], nwin);

        // ---- stats + finalize for batch b = w (first 64 workers) ----
        if (w < BATCH) {
            int b = w;
            int T = SEQ + p;
            if (p >= 1) wait_ctr(&g_ycnt, BATCH * p);   // need y_{p-1}

            float s = 0.f, ss = 0.f;
            for (int i = t; i < T; i += NT) {
                float v = (i < SEQ) ? __ldg(&g_x[b * XSTRIDE + i])
                                    : __ldcg(&g_x[b * XSTRIDE + i]);
                s += v; ss += v * v;
            }
            rs[t] = s; rss[t] = ss;
            __syncthreads();
            for (int o = NT / 2; o > 0; o >>= 1) {
                if (t < o) { rs[t] += rs[t + o]; rss[t] += rss[t + o]; }
                __syncthreads();
            }
            if (t == 0) {
                float mean = rs[0] / (float)T;
                float var  = (rss[0] - (float)T * mean * mean) / (float)(T - 1);
                thresh_sh = mean + 1.48f * sqrtf(fmaxf(var, 0.f));
            }

            wait_ctr(&g_hcnt, BATCH * (p + 1));     // H_p published (all batches)
            wait_ctr(&g_scnt[p], BATCH * NWIN);     // all 4096 windows of pred p done

            if (t < NWIN) starts_sh[t] = rand_start(p, b * NWIN + t, span);
            if (t < DM)   H_sh[t] = __ldcg(&g_H4[p * BATCH * DM + b * DM + t]);
            __syncthreads();

            if (t < NWIN) {
                const float* S = g_S4 + (p * BATCH * NWIN + b * NWIN + t) * DM;
                float d = 0.f;
#pragma unroll 4
                for (int h = 0; h < DM; h++) d += H_sh[h] * __ldcg(S + h);
                e_s[t] = d;
            }
            __syncthreads();

            if (t == 0) {
                float mx = -1e30f;
                for (int m = 0; m < NWIN; m++) mx = fmaxf(mx, e_s[m]);
                float se = 0.f;
                for (int m = 0; m < NWIN; m++) { float e = __expf(e_s[m] - mx); e_s[m] = e; se += e; }
                se_sh = se;
            }
            __syncthreads();

            if (t < DM) red[t] = H_sh[t] * __ldg(Wd + t);
            if (t < NWIN) {
                int idx = starts_sh[t] + WLEN;
                float q = (__ldcg(&g_x[b * XSTRIDE + idx]) > thresh_sh) ? 1.f : 0.f;
                qred[t] = q * e_s[t];
            }
            __syncthreads();

            for (int o = 64; o > 0; o >>= 1) {
                if (t < o) red[t] += red[t + o];
                if (o <= 32 && t < o) qred[t] += qred[t + o];
                __syncthreads();
            }

            if (t == 0) {
                float oval = red[0] + __ldg(bd);
                float sc = qred[0] / se_sh;
                float u = sigmoidf_(sc * __ldg(Wc) + __ldg(bc));
                float y = oval + u;
                g_x[b * XSTRIDE + SEQ + p] = y;
                out[b * PRED + p] = y;
                if (out_size >= 2 * BATCH * PRED) out[BATCH * PRED + b * PRED + p] = u;
                __threadfence();
                atomicAdd(&g_ycnt, 1);
            }
            __syncthreads();
        }
    }
}

__global__ void __launch_bounds__(NT, 1) persist_kernel(
    const float* __restrict__ Wi_g, const float* __restrict__ bi_g,
    const float* __restrict__ Wh_g, const float* __restrict__ bh_g,
    const float* __restrict__ Wi_w, const float* __restrict__ bi_w,
    const float* __restrict__ Wh_w, const float* __restrict__ bh_w,
    const float* __restrict__ Wd,   const float* __restrict__ bd,
    const float* __restrict__ Wc,   const float* __restrict__ bc,
    float* __restrict__ out, int out_size)
{
    int cta = blockIdx.x;
    if (cta < BATCH) {
        global_path(cta, Wi_g, bi_g, Wh_g, bh_g);
    } else {
        worker_path(cta - BATCH, Wi_w, bi_w, Wh_w, bh_w, Wd, bd, Wc, bc, out, out_size);
    }
}

// ---------------- launcher (default stream only) ----------------
extern "C" void kernel_launch(void* const* d_in, const int* in_sizes, int n_in,
                              void* d_out, int out_size) {
    const float* batch_x = (const float*)d_in[0];
    const float* Wi_g = (const float*)d_in[4];
    const float* Wh_g = (const float*)d_in[5];
    const float* bi_g = (const float*)d_in[6];
    const float* bh_g = (const float*)d_in[7];
    const float* Wi_w = (const float*)d_in[8];
    const float* Wh_w = (const float*)d_in[9];
    const float* bi_w = (const float*)d_in[10];
    const float* bh_w = (const float*)d_in[11];
    const float* Wd   = (const float*)d_in[12];
    const float* bd   = (const float*)d_in[13];
    const float* Wc   = (const float*)d_in[16];
    const float* bc   = (const float*)d_in[17];
    float* out = (float*)d_out;

    copy_x_kernel<<<(BATCH * SEQ + 255) / 256, 256>>>(batch_x);
    persist_kernel<<<NCTA, NT>>>(Wi_g, bi_g, Wh_g, bh_g,
                                 Wi_w, bi_w, Wh_w, bh_w,
                                 Wd, bd, Wc, bc, out, out_size);
}